// round 2
// baseline (speedup 1.0000x reference)
#include <cuda_runtime.h>
#include <cstdint>

#define B_ 2
#define T_ 2048
#define S_ 2048
#define E_ 1024
#define H_ 16
#define D_ 64
#define M_ (B_*T_)

// Scratch (device globals; no allocation allowed)
__device__ float g_q[B_*H_*T_*D_];
__device__ float g_k[B_*H_*S_*D_];
__device__ float g_v[B_*H_*S_*D_];
__device__ float g_attn[M_*E_];

// ---------------------------------------------------------------------------
// GEMM: out[m][n] = sum_k A[m][k] * W[n][k] + bias[n]
// M=4096, N=1024, K=1024.  64x64 tile, 256 threads, 4x4 per thread.
// headMajor=1: write out[((b*H+h)*T + t)*D + d] with m=(b,t), n=(h,d)
// ---------------------------------------------------------------------------
__global__ void __launch_bounds__(256) gemm_kernel(
    const float* __restrict__ A, const float* __restrict__ W,
    const float* __restrict__ bias, float* __restrict__ out, int headMajor)
{
    __shared__ float As[16][68];
    __shared__ float Ws[16][68];
    const int tid = threadIdx.x;
    const int tx = tid & 15, ty = tid >> 4;
    const int m0 = blockIdx.y * 64, n0 = blockIdx.x * 64;
    const int lr = tid >> 2;
    const int lk = (tid & 3) * 4;

    float acc[4][4];
#pragma unroll
    for (int i = 0; i < 4; i++)
#pragma unroll
        for (int j = 0; j < 4; j++) acc[i][j] = 0.f;

    const float* Arow = A + (size_t)(m0 + lr) * E_ + lk;
    const float* Wrow = W + (size_t)(n0 + lr) * E_ + lk;

    for (int kt = 0; kt < E_; kt += 16) {
        float4 a = *(const float4*)(Arow + kt);
        float4 w = *(const float4*)(Wrow + kt);
        As[lk + 0][lr] = a.x; As[lk + 1][lr] = a.y;
        As[lk + 2][lr] = a.z; As[lk + 3][lr] = a.w;
        Ws[lk + 0][lr] = w.x; Ws[lk + 1][lr] = w.y;
        Ws[lk + 2][lr] = w.z; Ws[lk + 3][lr] = w.w;
        __syncthreads();
#pragma unroll
        for (int k = 0; k < 16; k++) {
            float4 av = *(const float4*)&As[k][ty * 4];
            float4 wv = *(const float4*)&Ws[k][tx * 4];
            float am[4] = {av.x, av.y, av.z, av.w};
            float wm[4] = {wv.x, wv.y, wv.z, wv.w};
#pragma unroll
            for (int i = 0; i < 4; i++)
#pragma unroll
                for (int j = 0; j < 4; j++)
                    acc[i][j] += am[i] * wm[j];
        }
        __syncthreads();
    }

#pragma unroll
    for (int i = 0; i < 4; i++) {
        const int m = m0 + ty * 4 + i;
#pragma unroll
        for (int j = 0; j < 4; j++) {
            const int n = n0 + tx * 4 + j;
            const float vout = acc[i][j] + bias[n];
            if (headMajor) {
                const int b = m >> 11, t = m & 2047;
                const int h = n >> 6,  d = n & 63;
                out[(size_t)((b * H_ + h) * T_ + t) * D_ + d] = vout;
            } else {
                out[(size_t)m * E_ + n] = vout;
            }
        }
    }
}

// ---------------------------------------------------------------------------
// Flash attention with additive biases.
// Grid (T/64, H, B), 256 threads. Each CTA: 64 query rows of one (b,h).
// thread (r = tid/4, g = tid%4): owns row r, cols c in [g*16, g*16+16) for
// scores, and d in [g*16, g*16+16) for the output accumulator.
// ---------------------------------------------------------------------------
#define ATTN_SMEM_FLOATS (64*65 + 64*64 + 64*64 + 64*68 + 64)
#define ATTN_SMEM_BYTES  (ATTN_SMEM_FLOATS * 4)

__global__ void __launch_bounds__(256) attn_kernel(
    const float* __restrict__ spatial, const float* __restrict__ dirb,
    const float* __restrict__ amask, const unsigned char* __restrict__ pmask,
    float* __restrict__ outp)
{
    extern __shared__ float sm[];
    float* Qs = sm;               // [64][65]
    float* Ks = Qs + 64 * 65;     // [64][64], transposed: Ks[k*64 + c]
    float* Vs = Ks + 64 * 64;     // [64][64]: Vs[c*64 + d]
    float* Ss = Vs + 64 * 64;     // [64][68]
    float* Ms = Ss + 64 * 68;     // [64] additive pad mask

    const int tid = threadIdx.x;
    const int t0 = blockIdx.x * 64;
    const int h  = blockIdx.y;
    const int b  = blockIdx.z;
    const int r  = tid >> 2;
    const int g  = tid & 3;

    const float* qbase = g_q + (size_t)((b * H_ + h) * T_ + t0) * D_;
    const float* kbase = g_k + (size_t)(b * H_ + h) * S_ * D_;
    const float* vbase = g_v + (size_t)(b * H_ + h) * S_ * D_;

    // Load Q tile: thread loads 16 floats of row (tid/4)
    {
        const int rl = tid >> 2;
        const int ko = (tid & 3) * 16;
        const float* src = qbase + rl * D_ + ko;
#pragma unroll
        for (int jj = 0; jj < 4; jj++) {
            float4 qv = *(const float4*)(src + jj * 4);
            Qs[rl * 65 + ko + jj * 4 + 0] = qv.x;
            Qs[rl * 65 + ko + jj * 4 + 1] = qv.y;
            Qs[rl * 65 + ko + jj * 4 + 2] = qv.z;
            Qs[rl * 65 + ko + jj * 4 + 3] = qv.w;
        }
    }

    float m_i = -1e30f, l_i = 0.f;
    float acc[16];
#pragma unroll
    for (int i = 0; i < 16; i++) acc[i] = 0.f;

    const float scale = 0.125f;  // 1/sqrt(64)

    for (int s0 = 0; s0 < S_; s0 += 64) {
        // K tile, transposed to Ks[k][c]
        {
            const int c  = tid & 63;
            const int kq = tid >> 6;   // 0..3
            const float* src = kbase + (size_t)(s0 + c) * D_;
#pragma unroll
            for (int it = 0; it < 4; it++) {
                const int k4 = (kq + it * 4) * 4;
                float4 kv = *(const float4*)(src + k4);
                Ks[(k4 + 0) * 64 + c] = kv.x;
                Ks[(k4 + 1) * 64 + c] = kv.y;
                Ks[(k4 + 2) * 64 + c] = kv.z;
                Ks[(k4 + 3) * 64 + c] = kv.w;
            }
        }
        // V tile
        {
            const int d4 = (tid & 15) * 4;
            const int cv = tid >> 4;   // 0..15
#pragma unroll
            for (int it = 0; it < 4; it++) {
                const int c = cv + it * 16;
                *(float4*)&Vs[c * 64 + d4] =
                    *(const float4*)(vbase + (size_t)(s0 + c) * D_ + d4);
            }
        }
        if (tid < 64)
            Ms[tid] = pmask[b * S_ + s0 + tid] ? -1e30f : 0.f;
        __syncthreads();

        // ---- scores: sc[c'] = dot(Q[r], K[c]) for 16 consecutive c ----
        float sc[16];
#pragma unroll
        for (int i = 0; i < 16; i++) sc[i] = 0.f;
#pragma unroll 4
        for (int k = 0; k < 64; k++) {
            const float qv = Qs[r * 65 + k];
            const float* kr = &Ks[k * 64 + g * 16];
            float4 k0 = *(const float4*)(kr);
            float4 k1 = *(const float4*)(kr + 4);
            float4 k2 = *(const float4*)(kr + 8);
            float4 k3 = *(const float4*)(kr + 12);
            sc[0]  += qv * k0.x; sc[1]  += qv * k0.y; sc[2]  += qv * k0.z; sc[3]  += qv * k0.w;
            sc[4]  += qv * k1.x; sc[5]  += qv * k1.y; sc[6]  += qv * k1.z; sc[7]  += qv * k1.w;
            sc[8]  += qv * k2.x; sc[9]  += qv * k2.y; sc[10] += qv * k2.z; sc[11] += qv * k2.w;
            sc[12] += qv * k3.x; sc[13] += qv * k3.y; sc[14] += qv * k3.z; sc[15] += qv * k3.w;
        }

        // ---- biases + masks (each element read exactly once globally) ----
        const size_t brow = ((size_t)(b * H_ + h) * T_ + (t0 + r)) * S_ + s0 + g * 16;
        const float* sprow = spatial + brow;
        const float* drow  = dirb + brow;
        const float* arow  = amask + (size_t)(t0 + r) * S_ + s0 + g * 16;
#pragma unroll
        for (int ii = 0; ii < 4; ii++) {
            float4 sp = *(const float4*)(sprow + ii * 4);
            float4 dv = *(const float4*)(drow + ii * 4);
            float4 av = *(const float4*)(arow + ii * 4);
            sc[ii*4+0] = sc[ii*4+0] * scale + av.x + Ms[g*16 + ii*4 + 0] + sp.x + dv.x;
            sc[ii*4+1] = sc[ii*4+1] * scale + av.y + Ms[g*16 + ii*4 + 1] + sp.y + dv.y;
            sc[ii*4+2] = sc[ii*4+2] * scale + av.z + Ms[g*16 + ii*4 + 2] + sp.z + dv.z;
            sc[ii*4+3] = sc[ii*4+3] * scale + av.w + Ms[g*16 + ii*4 + 3] + sp.w + dv.w;
        }

        // ---- online softmax (row shared by 4 lanes of a quad) ----
        float mloc = m_i;
#pragma unroll
        for (int i = 0; i < 16; i++) mloc = fmaxf(mloc, sc[i]);
        mloc = fmaxf(mloc, __shfl_xor_sync(0xFFFFFFFFu, mloc, 1));
        mloc = fmaxf(mloc, __shfl_xor_sync(0xFFFFFFFFu, mloc, 2));

        const float alpha = __expf(m_i - mloc);
        float lsum = 0.f;
#pragma unroll
        for (int i = 0; i < 16; i++) {
            const float p = __expf(sc[i] - mloc);
            lsum += p;
            Ss[r * 68 + g * 16 + i] = p;
        }
        lsum += __shfl_xor_sync(0xFFFFFFFFu, lsum, 1);
        lsum += __shfl_xor_sync(0xFFFFFFFFu, lsum, 2);
        l_i = l_i * alpha + lsum;
        m_i = mloc;
#pragma unroll
        for (int i = 0; i < 16; i++) acc[i] *= alpha;
        __syncthreads();

        // ---- PV: acc[d'] += sum_c P[r][c] * V[c][d] ----
#pragma unroll 4
        for (int c = 0; c < 64; c++) {
            const float p = Ss[r * 68 + c];
            const float* vr = &Vs[c * 64 + g * 16];
            float4 v0 = *(const float4*)(vr);
            float4 v1 = *(const float4*)(vr + 4);
            float4 v2 = *(const float4*)(vr + 8);
            float4 v3 = *(const float4*)(vr + 12);
            acc[0]  += p * v0.x; acc[1]  += p * v0.y; acc[2]  += p * v0.z; acc[3]  += p * v0.w;
            acc[4]  += p * v1.x; acc[5]  += p * v1.y; acc[6]  += p * v1.z; acc[7]  += p * v1.w;
            acc[8]  += p * v2.x; acc[9]  += p * v2.y; acc[10] += p * v2.z; acc[11] += p * v2.w;
            acc[12] += p * v3.x; acc[13] += p * v3.y; acc[14] += p * v3.z; acc[15] += p * v3.w;
        }
        __syncthreads();
    }

    const float inv = 1.f / l_i;
    float* orow = outp + (size_t)(b * T_ + t0 + r) * E_ + h * D_ + g * 16;
#pragma unroll
    for (int ii = 0; ii < 4; ii++) {
        float4 o;
        o.x = acc[ii*4+0] * inv;
        o.y = acc[ii*4+1] * inv;
        o.z = acc[ii*4+2] * inv;
        o.w = acc[ii*4+3] * inv;
        *(float4*)(orow + ii * 4) = o;
    }
}

// ---------------------------------------------------------------------------
extern "C" void kernel_launch(void* const* d_in, const int* in_sizes, int n_in,
                              void* d_out, int out_size)
{
    const float* query = (const float*)d_in[0];
    const float* key   = (const float*)d_in[1];
    const float* value = (const float*)d_in[2];
    const float* spatial = (const float*)d_in[3];
    const float* dirb    = (const float*)d_in[4];
    const unsigned char* pmask = (const unsigned char*)d_in[5];
    const float* amask = (const float*)d_in[6];
    const float* Wq = (const float*)d_in[7];
    const float* bq = (const float*)d_in[8];
    const float* Wk = (const float*)d_in[9];
    const float* bk = (const float*)d_in[10];
    const float* Wv = (const float*)d_in[11];
    const float* bv = (const float*)d_in[12];
    const float* Wo = (const float*)d_in[13];
    const float* bo = (const float*)d_in[14];
    float* out = (float*)d_out;

    float *qp, *kp, *vp, *ap;
    cudaGetSymbolAddress((void**)&qp, g_q);
    cudaGetSymbolAddress((void**)&kp, g_k);
    cudaGetSymbolAddress((void**)&vp, g_v);
    cudaGetSymbolAddress((void**)&ap, g_attn);

    cudaFuncSetAttribute(attn_kernel,
                         cudaFuncAttributeMaxDynamicSharedMemorySize,
                         ATTN_SMEM_BYTES);

    const dim3 gb(E_ / 64, M_ / 64);   // (16, 64)
    gemm_kernel<<<gb, 256>>>(query, Wq, bq, qp, 1);
    gemm_kernel<<<gb, 256>>>(key,   Wk, bk, kp, 1);
    gemm_kernel<<<gb, 256>>>(value, Wv, bv, vp, 1);

    attn_kernel<<<dim3(T_ / 64, H_, B_), 256, ATTN_SMEM_BYTES>>>(
        spatial, dirb, amask, pmask, ap);

    gemm_kernel<<<gb, 256>>>(ap, Wo, bo, out, 0);
}

// round 3
// speedup vs baseline: 2.7877x; 2.7877x over previous
#include <cuda_runtime.h>
#include <cstdint>

#define B_ 2
#define T_ 2048
#define S_ 2048
#define E_ 1024
#define H_ 16
#define D_ 64
#define M_ (B_*T_)

// Scratch (device globals; no allocation allowed)
__device__ float g_q[B_*H_*T_*D_];
__device__ float g_k[B_*H_*S_*D_];
__device__ float g_v[B_*H_*S_*D_];
__device__ float g_attn[M_*E_];

// ---------------------------------------------------------------------------
// helpers
// ---------------------------------------------------------------------------
__device__ __forceinline__ uint32_t f2tf(float x) {
    uint32_t r;
    asm("cvt.rna.tf32.f32 %0, %1;" : "=r"(r) : "f"(x));
    return r;
}

__device__ __forceinline__ void mma_tf32(float c[4],
                                         uint32_t a0, uint32_t a1, uint32_t a2, uint32_t a3,
                                         uint32_t b0, uint32_t b1) {
    asm("mma.sync.aligned.m16n8k8.row.col.f32.tf32.tf32.f32 "
        "{%0,%1,%2,%3},{%4,%5,%6,%7},{%8,%9},{%0,%1,%2,%3};"
        : "+f"(c[0]), "+f"(c[1]), "+f"(c[2]), "+f"(c[3])
        : "r"(a0), "r"(a1), "r"(a2), "r"(a3), "r"(b0), "r"(b1));
}

// ---------------------------------------------------------------------------
// GEMM (tf32 tensor): out[m][n] = sum_k A[m][k] * W[n][k] + bias[n]
// M=4096, N=1024, K=1024. CTA tile 256x64, 8 warps, warp = 32 rows x 64 cols.
// headMajor=1: out[((b*H+h)*T + t)*D + d], m=(b,t), n=(h,d)
// ---------------------------------------------------------------------------
__global__ void __launch_bounds__(256) gemm_tc(
    const float* __restrict__ A, const float* __restrict__ W,
    const float* __restrict__ bias, float* __restrict__ out, int headMajor)
{
    __shared__ uint32_t As[256 * 36];
    __shared__ uint32_t Ws[64 * 36];

    const int tid  = threadIdx.x;
    const int lane = tid & 31;
    const int wid  = tid >> 5;
    const int m0   = blockIdx.y * 256;
    const int n0   = blockIdx.x * 64;
    const int qg   = lane >> 2;   // quad group 0..7
    const int qt   = lane & 3;    // thread in quad 0..3

    float acc[2][8][4];
#pragma unroll
    for (int mt = 0; mt < 2; mt++)
#pragma unroll
        for (int j = 0; j < 8; j++)
#pragma unroll
            for (int i = 0; i < 4; i++) acc[mt][j][i] = 0.f;

    const float* Arow = A + (size_t)(m0 + tid) * E_;
    const float* Wrow = W + (size_t)(n0 + (tid >> 2)) * E_ + (tid & 3) * 8;

    for (int kt = 0; kt < E_; kt += 32) {
        // stage A: thread loads its own row, 32 k-values
#pragma unroll
        for (int i = 0; i < 8; i++) {
            float4 v = *(const float4*)(Arow + kt + i * 4);
            uint4 u = {f2tf(v.x), f2tf(v.y), f2tf(v.z), f2tf(v.w)};
            *(uint4*)&As[tid * 36 + i * 4] = u;
        }
        // stage W: 64 rows x 32, thread loads 8
#pragma unroll
        for (int i = 0; i < 2; i++) {
            float4 v = *(const float4*)(Wrow + kt + i * 4);
            uint4 u = {f2tf(v.x), f2tf(v.y), f2tf(v.z), f2tf(v.w)};
            *(uint4*)&Ws[(tid >> 2) * 36 + (tid & 3) * 8 + i * 4] = u;
        }
        __syncthreads();

#pragma unroll
        for (int kk = 0; kk < 4; kk++) {
            uint32_t a[2][4];
#pragma unroll
            for (int mt = 0; mt < 2; mt++) {
                const int ar = wid * 32 + mt * 16 + qg;
                const int ac = kk * 8 + qt;
                a[mt][0] = As[ar * 36 + ac];
                a[mt][1] = As[(ar + 8) * 36 + ac];
                a[mt][2] = As[ar * 36 + ac + 4];
                a[mt][3] = As[(ar + 8) * 36 + ac + 4];
            }
#pragma unroll
            for (int j = 0; j < 8; j++) {
                const int br = j * 8 + qg;
                const int bc = kk * 8 + qt;
                uint32_t b0 = Ws[br * 36 + bc];
                uint32_t b1 = Ws[br * 36 + bc + 4];
                mma_tf32(acc[0][j], a[0][0], a[0][1], a[0][2], a[0][3], b0, b1);
                mma_tf32(acc[1][j], a[1][0], a[1][1], a[1][2], a[1][3], b0, b1);
            }
        }
        __syncthreads();
    }

    // epilogue
#pragma unroll
    for (int mt = 0; mt < 2; mt++) {
        const int row0 = m0 + wid * 32 + mt * 16 + qg;
#pragma unroll
        for (int j = 0; j < 8; j++) {
            const int col = n0 + j * 8 + 2 * qt;
            const float bz0 = bias[col], bz1 = bias[col + 1];
            float v00 = acc[mt][j][0] + bz0, v01 = acc[mt][j][1] + bz1;
            float v10 = acc[mt][j][2] + bz0, v11 = acc[mt][j][3] + bz1;
            if (headMajor) {
                const int h = col >> 6, d = col & 63;
                {
                    const int b = row0 >> 11, t = row0 & 2047;
                    float2 o = {v00, v01};
                    *(float2*)&out[(size_t)((b * H_ + h) * T_ + t) * D_ + d] = o;
                }
                {
                    const int r1 = row0 + 8;
                    const int b = r1 >> 11, t = r1 & 2047;
                    float2 o = {v10, v11};
                    *(float2*)&out[(size_t)((b * H_ + h) * T_ + t) * D_ + d] = o;
                }
            } else {
                float2 o0 = {v00, v01};
                float2 o1 = {v10, v11};
                *(float2*)&out[(size_t)row0 * E_ + col] = o0;
                *(float2*)&out[(size_t)(row0 + 8) * E_ + col] = o1;
            }
        }
    }
}

// ---------------------------------------------------------------------------
// Flash attention, tf32 tensor cores.
// Grid (T/128, H, B), 256 threads = 8 warps; warp owns 16 full q-rows.
// Q fragments persist in registers; QP smem buffer reused as warp-private P.
// ---------------------------------------------------------------------------
#define ATTN_SMEM_U32 (128*68 + 64*68 + 64*72 + 64)
#define ATTN_SMEM_BYTES (ATTN_SMEM_U32 * 4)

__global__ void __launch_bounds__(256) attn_tc(
    const float* __restrict__ spatial, const float* __restrict__ dirb,
    const float* __restrict__ amask, const unsigned char* __restrict__ pmask,
    float* __restrict__ outp)
{
    extern __shared__ uint32_t smu[];
    uint32_t* QP = smu;                 // [128][68]  Q staging, then P
    uint32_t* Ks = QP + 128 * 68;       // [64][68]   K[s][d]
    uint32_t* Vs = Ks + 64 * 68;        // [64][72]   V[s][d]
    float*    Ms = (float*)(Vs + 64 * 72); // [64]    additive pad mask

    const int tid  = threadIdx.x;
    const int lane = tid & 31;
    const int wid  = tid >> 5;
    const int qg   = lane >> 2;
    const int qt   = lane & 3;
    const int t0   = blockIdx.x * 128;
    const int h    = blockIdx.y;
    const int b    = blockIdx.z;
    const int r0   = wid * 16;

    const float* qbase = g_q + (size_t)((b * H_ + h) * T_ + t0) * D_;
    const float* kbase = g_k + (size_t)(b * H_ + h) * S_ * D_;
    const float* vbase = g_v + (size_t)(b * H_ + h) * S_ * D_;

    // stage Q tile (128x64) as tf32 (warp-private rows: tid>>1 in [16w,16w+16))
    {
        const int r = tid >> 1, c0 = (tid & 1) * 32;
        const float* src = qbase + r * D_ + c0;
#pragma unroll
        for (int i = 0; i < 8; i++) {
            float4 v = *(const float4*)(src + i * 4);
            uint4 u = {f2tf(v.x), f2tf(v.y), f2tf(v.z), f2tf(v.w)};
            *(uint4*)&QP[r * 68 + c0 + i * 4] = u;
        }
    }
    __syncthreads();

    // Q fragments, persistent (32 regs)
    uint32_t qa[8][4];
#pragma unroll
    for (int kk = 0; kk < 8; kk++) {
        const int ar = r0 + qg, ac = kk * 8 + qt;
        qa[kk][0] = QP[ar * 68 + ac];
        qa[kk][1] = QP[(ar + 8) * 68 + ac];
        qa[kk][2] = QP[ar * 68 + ac + 4];
        qa[kk][3] = QP[(ar + 8) * 68 + ac + 4];
    }

    float mrow[2] = {-1e30f, -1e30f};
    float lrow[2] = {0.f, 0.f};
    float oacc[8][4];
#pragma unroll
    for (int j = 0; j < 8; j++)
#pragma unroll
        for (int i = 0; i < 4; i++) oacc[j][i] = 0.f;

    const int ra = t0 + r0 + qg;       // global t for c0/c1
    const int rb = ra + 8;             // global t for c2/c3
    const size_t bh = (size_t)(b * H_ + h) * T_;
    const float* spA = spatial + (bh + ra) * S_;
    const float* spB = spatial + (bh + rb) * S_;
    const float* dbA = dirb + (bh + ra) * S_;
    const float* dbB = dirb + (bh + rb) * S_;
    const float* amA = amask + (size_t)ra * S_;
    const float* amB = amask + (size_t)rb * S_;

    for (int s0 = 0; s0 < S_; s0 += 64) {
        __syncthreads();   // protect Ks/Vs from prior iteration's reads

        // stage K/V tiles (64x64 each) as tf32: thread row tid>>2, 16 cols
        {
            const int r = tid >> 2, c0 = (tid & 3) * 16;
            const float* ksrc = kbase + (size_t)(s0 + r) * D_ + c0;
            const float* vsrc = vbase + (size_t)(s0 + r) * D_ + c0;
#pragma unroll
            for (int i = 0; i < 4; i++) {
                float4 kv = *(const float4*)(ksrc + i * 4);
                uint4 ku = {f2tf(kv.x), f2tf(kv.y), f2tf(kv.z), f2tf(kv.w)};
                *(uint4*)&Ks[r * 68 + c0 + i * 4] = ku;
                float4 vv = *(const float4*)(vsrc + i * 4);
                uint4 vu = {f2tf(vv.x), f2tf(vv.y), f2tf(vv.z), f2tf(vv.w)};
                *(uint4*)&Vs[r * 72 + c0 + i * 4] = vu;
            }
        }
        if (tid < 64)
            Ms[tid] = pmask[b * S_ + s0 + tid] ? -1e30f : 0.f;
        __syncthreads();

        // ---- QK^T: S[16 x 64] per warp ----
        float sacc[8][4];
#pragma unroll
        for (int j = 0; j < 8; j++)
#pragma unroll
            for (int i = 0; i < 4; i++) sacc[j][i] = 0.f;

#pragma unroll
        for (int kk = 0; kk < 8; kk++) {
#pragma unroll
            for (int j = 0; j < 8; j++) {
                const int br = j * 8 + qg;       // s-col
                const int bc = kk * 8 + qt;      // d
                uint32_t b0 = Ks[br * 68 + bc];
                uint32_t b1 = Ks[br * 68 + bc + 4];
                mma_tf32(sacc[j], qa[kk][0], qa[kk][1], qa[kk][2], qa[kk][3], b0, b1);
            }
        }

        // ---- scale + biases + masks (each bias element read exactly once) ----
#pragma unroll
        for (int j = 0; j < 8; j++) {
            const int c = j * 8 + 2 * qt;
            const int gc = s0 + c;
            float2 s1 = *(const float2*)(spA + gc);
            float2 s2 = *(const float2*)(spB + gc);
            float2 d1 = *(const float2*)(dbA + gc);
            float2 d2 = *(const float2*)(dbB + gc);
            float2 a1 = *(const float2*)(amA + gc);
            float2 a2 = *(const float2*)(amB + gc);
            const float mk0 = Ms[c], mk1 = Ms[c + 1];
            sacc[j][0] = sacc[j][0] * 0.125f + a1.x + s1.x + d1.x + mk0;
            sacc[j][1] = sacc[j][1] * 0.125f + a1.y + s1.y + d1.y + mk1;
            sacc[j][2] = sacc[j][2] * 0.125f + a2.x + s2.x + d2.x + mk0;
            sacc[j][3] = sacc[j][3] * 0.125f + a2.y + s2.y + d2.y + mk1;
        }

        // ---- online softmax (row = 4 quad lanes) ----
        float mx0 = mrow[0], mx1 = mrow[1];
#pragma unroll
        for (int j = 0; j < 8; j++) {
            mx0 = fmaxf(mx0, fmaxf(sacc[j][0], sacc[j][1]));
            mx1 = fmaxf(mx1, fmaxf(sacc[j][2], sacc[j][3]));
        }
        mx0 = fmaxf(mx0, __shfl_xor_sync(0xFFFFFFFFu, mx0, 1));
        mx0 = fmaxf(mx0, __shfl_xor_sync(0xFFFFFFFFu, mx0, 2));
        mx1 = fmaxf(mx1, __shfl_xor_sync(0xFFFFFFFFu, mx1, 1));
        mx1 = fmaxf(mx1, __shfl_xor_sync(0xFFFFFFFFu, mx1, 2));

        const float al0 = __expf(mrow[0] - mx0);
        const float al1 = __expf(mrow[1] - mx1);
        float ls0 = 0.f, ls1 = 0.f;
#pragma unroll
        for (int j = 0; j < 8; j++) {
            sacc[j][0] = __expf(sacc[j][0] - mx0);
            sacc[j][1] = __expf(sacc[j][1] - mx0);
            sacc[j][2] = __expf(sacc[j][2] - mx1);
            sacc[j][3] = __expf(sacc[j][3] - mx1);
            ls0 += sacc[j][0] + sacc[j][1];
            ls1 += sacc[j][2] + sacc[j][3];
        }
        ls0 += __shfl_xor_sync(0xFFFFFFFFu, ls0, 1);
        ls0 += __shfl_xor_sync(0xFFFFFFFFu, ls0, 2);
        ls1 += __shfl_xor_sync(0xFFFFFFFFu, ls1, 1);
        ls1 += __shfl_xor_sync(0xFFFFFFFFu, ls1, 2);
        mrow[0] = mx0; mrow[1] = mx1;
        lrow[0] = lrow[0] * al0 + ls0;
        lrow[1] = lrow[1] * al1 + ls1;
#pragma unroll
        for (int j = 0; j < 8; j++) {
            oacc[j][0] *= al0; oacc[j][1] *= al0;
            oacc[j][2] *= al1; oacc[j][3] *= al1;
        }

        // ---- P -> smem (warp-private rows r0..r0+15 of QP buffer) ----
        __syncwarp();   // prior PV reads of QP done before overwrite
#pragma unroll
        for (int j = 0; j < 8; j++) {
            const int pr = r0 + qg;
            const int pc = j * 8 + 2 * qt;
            uint2 p0 = {f2tf(sacc[j][0]), f2tf(sacc[j][1])};
            uint2 p1 = {f2tf(sacc[j][2]), f2tf(sacc[j][3])};
            *(uint2*)&QP[pr * 68 + pc] = p0;
            *(uint2*)&QP[(pr + 8) * 68 + pc] = p1;
        }
        __syncwarp();

        // ---- PV: O += P[16 x 64] * V[64 x 64] ----
#pragma unroll
        for (int kk = 0; kk < 8; kk++) {
            const int ar = r0 + qg, ac = kk * 8 + qt;
            uint32_t a0 = QP[ar * 68 + ac];
            uint32_t a1 = QP[(ar + 8) * 68 + ac];
            uint32_t a2 = QP[ar * 68 + ac + 4];
            uint32_t a3 = QP[(ar + 8) * 68 + ac + 4];
#pragma unroll
            for (int j = 0; j < 8; j++) {
                const int br = kk * 8 + qt;     // s (k-dim)
                const int bc = j * 8 + qg;      // d (n-dim)
                uint32_t b0 = Vs[br * 72 + bc];
                uint32_t b1 = Vs[(br + 4) * 72 + bc];
                mma_tf32(oacc[j], a0, a1, a2, a3, b0, b1);
            }
        }
    }

    // ---- epilogue ----
    const float inv0 = 1.f / lrow[0];
    const float inv1 = 1.f / lrow[1];
    float* oA = outp + (size_t)(b * T_ + ra) * E_ + h * D_;
    float* oB = outp + (size_t)(b * T_ + rb) * E_ + h * D_;
#pragma unroll
    for (int j = 0; j < 8; j++) {
        const int c = j * 8 + 2 * qt;
        float2 o0 = {oacc[j][0] * inv0, oacc[j][1] * inv0};
        float2 o1 = {oacc[j][2] * inv1, oacc[j][3] * inv1};
        *(float2*)(oA + c) = o0;
        *(float2*)(oB + c) = o1;
    }
}

// ---------------------------------------------------------------------------
extern "C" void kernel_launch(void* const* d_in, const int* in_sizes, int n_in,
                              void* d_out, int out_size)
{
    const float* query = (const float*)d_in[0];
    const float* key   = (const float*)d_in[1];
    const float* value = (const float*)d_in[2];
    const float* spatial = (const float*)d_in[3];
    const float* dirb    = (const float*)d_in[4];
    const unsigned char* pmask = (const unsigned char*)d_in[5];
    const float* amask = (const float*)d_in[6];
    const float* Wq = (const float*)d_in[7];
    const float* bq = (const float*)d_in[8];
    const float* Wk = (const float*)d_in[9];
    const float* bk = (const float*)d_in[10];
    const float* Wv = (const float*)d_in[11];
    const float* bv = (const float*)d_in[12];
    const float* Wo = (const float*)d_in[13];
    const float* bo = (const float*)d_in[14];
    float* out = (float*)d_out;

    float *qp, *kp, *vp, *ap;
    cudaGetSymbolAddress((void**)&qp, g_q);
    cudaGetSymbolAddress((void**)&kp, g_k);
    cudaGetSymbolAddress((void**)&vp, g_v);
    cudaGetSymbolAddress((void**)&ap, g_attn);

    cudaFuncSetAttribute(attn_tc,
                         cudaFuncAttributeMaxDynamicSharedMemorySize,
                         ATTN_SMEM_BYTES);

    const dim3 gb(E_ / 64, M_ / 256);   // (16, 16)
    gemm_tc<<<gb, 256>>>(query, Wq, bq, qp, 1);
    gemm_tc<<<gb, 256>>>(key,   Wk, bk, kp, 1);
    gemm_tc<<<gb, 256>>>(value, Wv, bv, vp, 1);

    attn_tc<<<dim3(T_ / 128, H_, B_), 256, ATTN_SMEM_BYTES>>>(
        spatial, dirb, amask, pmask, ap);

    gemm_tc<<<gb, 256>>>(ap, Wo, bo, out, 0);
}

// round 4
// speedup vs baseline: 4.2751x; 1.5335x over previous
#include <cuda_runtime.h>
#include <cstdint>

#define B_ 2
#define T_ 2048
#define S_ 2048
#define E_ 1024
#define H_ 16
#define D_ 64
#define M_ (B_*T_)

// Scratch (device globals; no allocation allowed)
__device__ float g_q[B_*H_*T_*D_];
__device__ float g_k[B_*H_*S_*D_];
__device__ float g_v[B_*H_*S_*D_];
__device__ float g_attn[M_*E_];

// ---------------------------------------------------------------------------
// helpers
// ---------------------------------------------------------------------------
__device__ __forceinline__ uint32_t f2tf(float x) {
    uint32_t r;
    asm("cvt.rna.tf32.f32 %0, %1;" : "=r"(r) : "f"(x));
    return r;
}

__device__ __forceinline__ void mma_tf32(float c[4],
                                         uint32_t a0, uint32_t a1, uint32_t a2, uint32_t a3,
                                         uint32_t b0, uint32_t b1) {
    asm("mma.sync.aligned.m16n8k8.row.col.f32.tf32.tf32.f32 "
        "{%0,%1,%2,%3},{%4,%5,%6,%7},{%8,%9},{%0,%1,%2,%3};"
        : "+f"(c[0]), "+f"(c[1]), "+f"(c[2]), "+f"(c[3])
        : "r"(a0), "r"(a1), "r"(a2), "r"(a3), "r"(b0), "r"(b1));
}

__device__ __forceinline__ void cp16(void* smem_dst, const void* gmem_src) {
    uint32_t s = (uint32_t)__cvta_generic_to_shared(smem_dst);
    asm volatile("cp.async.cg.shared.global [%0], [%1], 16;" :: "r"(s), "l"(gmem_src));
}
__device__ __forceinline__ void cp_commit() {
    asm volatile("cp.async.commit_group;");
}
__device__ __forceinline__ void cp_wait0() {
    asm volatile("cp.async.wait_group 0;");
}
__device__ __forceinline__ void cp_wait1() {
    asm volatile("cp.async.wait_group 1;");
}

// ---------------------------------------------------------------------------
// GEMM (tf32 tensor, cp.async double-buffered):
// out[m][n] = sum_k A[m][k]*W[n][k] + bias[n]
// M=4096, N=1024, K=1024. CTA tile 256x64, 8 warps, warp = 32 rows x 64 cols.
// ---------------------------------------------------------------------------
#define GEMM_SMEM_FLOATS (2*(256*36) + 2*(64*36))
#define GEMM_SMEM_BYTES  (GEMM_SMEM_FLOATS * 4)

__global__ void __launch_bounds__(256, 2) gemm_tc(
    const float* __restrict__ A, const float* __restrict__ W,
    const float* __restrict__ bias, float* __restrict__ out, int headMajor)
{
    extern __shared__ float gsm[];
    float* As = gsm;                 // [2][256][36]
    float* Ws = gsm + 2 * 256 * 36;  // [2][64][36]

    const int tid  = threadIdx.x;
    const int lane = tid & 31;
    const int wid  = tid >> 5;
    const int m0   = blockIdx.y * 256;
    const int n0   = blockIdx.x * 64;
    const int qg   = lane >> 2;
    const int qt   = lane & 3;

    float acc[2][8][4];
#pragma unroll
    for (int mt = 0; mt < 2; mt++)
#pragma unroll
        for (int j = 0; j < 8; j++)
#pragma unroll
            for (int i = 0; i < 4; i++) acc[mt][j][i] = 0.f;

    const float* Arow = A + (size_t)(m0 + tid) * E_;
    const float* Wrow = W + (size_t)(n0 + (tid >> 2)) * E_ + (tid & 3) * 8;
    float* Asr = As + tid * 36;
    float* Wsr = Ws + (tid >> 2) * 36 + (tid & 3) * 8;

    // prologue: stage k-step 0 into buffer 0
#pragma unroll
    for (int i = 0; i < 8; i++) cp16(Asr + i * 4, Arow + i * 4);
#pragma unroll
    for (int i = 0; i < 2; i++) cp16(Wsr + i * 4, Wrow + i * 4);
    cp_commit();

    const int NSTEP = E_ / 32;
    for (int s = 0; s < NSTEP; s++) {
        const int buf  = s & 1;
        const int nbuf = buf ^ 1;
        if (s + 1 < NSTEP) {
            const int kt = (s + 1) * 32;
#pragma unroll
            for (int i = 0; i < 8; i++)
                cp16(Asr + nbuf * 256 * 36 + i * 4, Arow + kt + i * 4);
#pragma unroll
            for (int i = 0; i < 2; i++)
                cp16(Wsr + nbuf * 64 * 36 + i * 4, Wrow + kt + i * 4);
            cp_commit();
            cp_wait1();
        } else {
            cp_wait0();
        }
        __syncthreads();

        const float* Ab = As + buf * 256 * 36;
        const float* Wb = Ws + buf * 64 * 36;
#pragma unroll
        for (int kk = 0; kk < 4; kk++) {
            uint32_t a[2][4];
#pragma unroll
            for (int mt = 0; mt < 2; mt++) {
                const int ar = wid * 32 + mt * 16 + qg;
                const int ac = kk * 8 + qt;
                a[mt][0] = f2tf(Ab[ar * 36 + ac]);
                a[mt][1] = f2tf(Ab[(ar + 8) * 36 + ac]);
                a[mt][2] = f2tf(Ab[ar * 36 + ac + 4]);
                a[mt][3] = f2tf(Ab[(ar + 8) * 36 + ac + 4]);
            }
#pragma unroll
            for (int j = 0; j < 8; j++) {
                const int br = j * 8 + qg;
                const int bc = kk * 8 + qt;
                uint32_t b0 = f2tf(Wb[br * 36 + bc]);
                uint32_t b1 = f2tf(Wb[br * 36 + bc + 4]);
                mma_tf32(acc[0][j], a[0][0], a[0][1], a[0][2], a[0][3], b0, b1);
                mma_tf32(acc[1][j], a[1][0], a[1][1], a[1][2], a[1][3], b0, b1);
            }
        }
        __syncthreads();
    }

    // epilogue
#pragma unroll
    for (int mt = 0; mt < 2; mt++) {
        const int row0 = m0 + wid * 32 + mt * 16 + qg;
#pragma unroll
        for (int j = 0; j < 8; j++) {
            const int col = n0 + j * 8 + 2 * qt;
            const float bz0 = bias[col], bz1 = bias[col + 1];
            float v00 = acc[mt][j][0] + bz0, v01 = acc[mt][j][1] + bz1;
            float v10 = acc[mt][j][2] + bz0, v11 = acc[mt][j][3] + bz1;
            if (headMajor) {
                const int h = col >> 6, d = col & 63;
                {
                    const int b = row0 >> 11, t = row0 & 2047;
                    float2 o = {v00, v01};
                    *(float2*)&out[(size_t)((b * H_ + h) * T_ + t) * D_ + d] = o;
                }
                {
                    const int r1 = row0 + 8;
                    const int b = r1 >> 11, t = r1 & 2047;
                    float2 o = {v10, v11};
                    *(float2*)&out[(size_t)((b * H_ + h) * T_ + t) * D_ + d] = o;
                }
            } else {
                float2 o0 = {v00, v01};
                float2 o1 = {v10, v11};
                *(float2*)&out[(size_t)row0 * E_ + col] = o0;
                *(float2*)&out[(size_t)(row0 + 8) * E_ + col] = o1;
            }
        }
    }
}

// ---------------------------------------------------------------------------
// Flash attention, tf32 tensor cores, 2 CTAs/SM.
// Grid (T/128, H, B), 256 threads = 8 warps; warp owns 16 full q-rows.
// Q kept in smem (raw fp32); fragments reloaded per tile. Separate P buffer.
// ---------------------------------------------------------------------------
// u32 offsets within dynamic smem:
#define AQ_OFF 0                       // Qs  [128][68] fp32
#define AK_OFF (128*68)                // Ks  [64][68]  fp32
#define AV_OFF (AK_OFF + 64*68)        // Vs  [64][72]  fp32
#define AP_OFF (AV_OFF + 64*72)        // Ps  [128][68] tf32(u32)
#define AM_OFF (AP_OFF + 128*68)       // Ms  [64]      fp32
#define ATTN_SMEM_U32 (AM_OFF + 64)
#define ATTN_SMEM_BYTES (ATTN_SMEM_U32 * 4)

__global__ void __launch_bounds__(256, 2) attn_tc(
    const float* __restrict__ spatial, const float* __restrict__ dirb,
    const float* __restrict__ amask, const unsigned char* __restrict__ pmask,
    float* __restrict__ outp)
{
    extern __shared__ uint32_t smu[];
    float*    Qs = (float*)(smu + AQ_OFF);
    float*    Ks = (float*)(smu + AK_OFF);
    float*    Vs = (float*)(smu + AV_OFF);
    uint32_t* Ps = smu + AP_OFF;
    float*    Ms = (float*)(smu + AM_OFF);

    const int tid  = threadIdx.x;
    const int lane = tid & 31;
    const int wid  = tid >> 5;
    const int qg   = lane >> 2;
    const int qt   = lane & 3;
    const int t0   = blockIdx.x * 128;
    const int h    = blockIdx.y;
    const int b    = blockIdx.z;
    const int r0   = wid * 16;

    const float* qbase = g_q + (size_t)((b * H_ + h) * T_ + t0) * D_;
    const float* kbase = g_k + (size_t)(b * H_ + h) * S_ * D_;
    const float* vbase = g_v + (size_t)(b * H_ + h) * S_ * D_;

    // stage Q tile (128x64 fp32) via cp.async
    {
        const int r = tid >> 1, c0 = (tid & 1) * 32;
        const float* src = qbase + r * D_ + c0;
        float* dst = Qs + r * 68 + c0;
#pragma unroll
        for (int i = 0; i < 8; i++) cp16(dst + i * 4, src + i * 4);
        cp_commit();
    }

    float mrow[2] = {-1e30f, -1e30f};
    float lrow[2] = {0.f, 0.f};
    float oacc[8][4];
#pragma unroll
    for (int j = 0; j < 8; j++)
#pragma unroll
        for (int i = 0; i < 4; i++) oacc[j][i] = 0.f;

    const int ra = t0 + r0 + qg;
    const int rb = ra + 8;
    const size_t bh = (size_t)(b * H_ + h) * T_;
    const float* spA = spatial + (bh + ra) * S_;
    const float* spB = spatial + (bh + rb) * S_;
    const float* dbA = dirb + (bh + ra) * S_;
    const float* dbB = dirb + (bh + rb) * S_;
    const float* amA = amask + (size_t)ra * S_;
    const float* amB = amask + (size_t)rb * S_;

    for (int s0 = 0; s0 < S_; s0 += 64) {
        __syncthreads();   // all warps done with prior Ks/Vs

        // stage K/V tiles (64x64 fp32 each) via cp.async
        {
            const int r = tid >> 2, c0 = (tid & 3) * 16;
            const float* ksrc = kbase + (size_t)(s0 + r) * D_ + c0;
            const float* vsrc = vbase + (size_t)(s0 + r) * D_ + c0;
            float* kdst = Ks + r * 68 + c0;
            float* vdst = Vs + r * 72 + c0;
#pragma unroll
            for (int i = 0; i < 4; i++) cp16(kdst + i * 4, ksrc + i * 4);
#pragma unroll
            for (int i = 0; i < 4; i++) cp16(vdst + i * 4, vsrc + i * 4);
        }
        if (tid < 64)
            Ms[tid] = pmask[b * S_ + s0 + tid] ? -1e30f : 0.f;
        cp_commit();
        cp_wait0();        // also covers Q staging on first iteration
        __syncthreads();

        // ---- QK^T: S[16 x 64] per warp ----
        float sacc[8][4];
#pragma unroll
        for (int j = 0; j < 8; j++)
#pragma unroll
            for (int i = 0; i < 4; i++) sacc[j][i] = 0.f;

#pragma unroll
        for (int kk = 0; kk < 8; kk++) {
            const int ar = r0 + qg, ac = kk * 8 + qt;
            uint32_t a0 = f2tf(Qs[ar * 68 + ac]);
            uint32_t a1 = f2tf(Qs[(ar + 8) * 68 + ac]);
            uint32_t a2 = f2tf(Qs[ar * 68 + ac + 4]);
            uint32_t a3 = f2tf(Qs[(ar + 8) * 68 + ac + 4]);
#pragma unroll
            for (int j = 0; j < 8; j++) {
                const int br = j * 8 + qg;
                const int bc = kk * 8 + qt;
                uint32_t b0 = f2tf(Ks[br * 68 + bc]);
                uint32_t b1 = f2tf(Ks[br * 68 + bc + 4]);
                mma_tf32(sacc[j], a0, a1, a2, a3, b0, b1);
            }
        }

        // ---- scale + biases + masks (each bias element read exactly once) ----
#pragma unroll
        for (int j = 0; j < 8; j++) {
            const int c = j * 8 + 2 * qt;
            const int gc = s0 + c;
            float2 s1 = *(const float2*)(spA + gc);
            float2 s2 = *(const float2*)(spB + gc);
            float2 d1 = *(const float2*)(dbA + gc);
            float2 d2 = *(const float2*)(dbB + gc);
            float2 a1 = *(const float2*)(amA + gc);
            float2 a2 = *(const float2*)(amB + gc);
            const float mk0 = Ms[c], mk1 = Ms[c + 1];
            sacc[j][0] = sacc[j][0] * 0.125f + a1.x + s1.x + d1.x + mk0;
            sacc[j][1] = sacc[j][1] * 0.125f + a1.y + s1.y + d1.y + mk1;
            sacc[j][2] = sacc[j][2] * 0.125f + a2.x + s2.x + d2.x + mk0;
            sacc[j][3] = sacc[j][3] * 0.125f + a2.y + s2.y + d2.y + mk1;
        }

        // ---- online softmax (row = 4 quad lanes) ----
        float mx0 = mrow[0], mx1 = mrow[1];
#pragma unroll
        for (int j = 0; j < 8; j++) {
            mx0 = fmaxf(mx0, fmaxf(sacc[j][0], sacc[j][1]));
            mx1 = fmaxf(mx1, fmaxf(sacc[j][2], sacc[j][3]));
        }
        mx0 = fmaxf(mx0, __shfl_xor_sync(0xFFFFFFFFu, mx0, 1));
        mx0 = fmaxf(mx0, __shfl_xor_sync(0xFFFFFFFFu, mx0, 2));
        mx1 = fmaxf(mx1, __shfl_xor_sync(0xFFFFFFFFu, mx1, 1));
        mx1 = fmaxf(mx1, __shfl_xor_sync(0xFFFFFFFFu, mx1, 2));

        const float al0 = __expf(mrow[0] - mx0);
        const float al1 = __expf(mrow[1] - mx1);
        float ls0 = 0.f, ls1 = 0.f;
#pragma unroll
        for (int j = 0; j < 8; j++) {
            sacc[j][0] = __expf(sacc[j][0] - mx0);
            sacc[j][1] = __expf(sacc[j][1] - mx0);
            sacc[j][2] = __expf(sacc[j][2] - mx1);
            sacc[j][3] = __expf(sacc[j][3] - mx1);
            ls0 += sacc[j][0] + sacc[j][1];
            ls1 += sacc[j][2] + sacc[j][3];
        }
        ls0 += __shfl_xor_sync(0xFFFFFFFFu, ls0, 1);
        ls0 += __shfl_xor_sync(0xFFFFFFFFu, ls0, 2);
        ls1 += __shfl_xor_sync(0xFFFFFFFFu, ls1, 1);
        ls1 += __shfl_xor_sync(0xFFFFFFFFu, ls1, 2);
        mrow[0] = mx0; mrow[1] = mx1;
        lrow[0] = lrow[0] * al0 + ls0;
        lrow[1] = lrow[1] * al1 + ls1;
#pragma unroll
        for (int j = 0; j < 8; j++) {
            oacc[j][0] *= al0; oacc[j][1] *= al0;
            oacc[j][2] *= al1; oacc[j][3] *= al1;
        }

        // ---- P -> smem (warp-private rows) ----
#pragma unroll
        for (int j = 0; j < 8; j++) {
            const int pr = r0 + qg;
            const int pc = j * 8 + 2 * qt;
            uint2 p0 = {f2tf(sacc[j][0]), f2tf(sacc[j][1])};
            uint2 p1 = {f2tf(sacc[j][2]), f2tf(sacc[j][3])};
            *(uint2*)&Ps[pr * 68 + pc] = p0;
            *(uint2*)&Ps[(pr + 8) * 68 + pc] = p1;
        }
        __syncwarp();

        // ---- PV: O += P[16 x 64] * V[64 x 64] ----
#pragma unroll
        for (int kk = 0; kk < 8; kk++) {
            const int ar = r0 + qg, ac = kk * 8 + qt;
            uint32_t a0 = Ps[ar * 68 + ac];
            uint32_t a1 = Ps[(ar + 8) * 68 + ac];
            uint32_t a2 = Ps[ar * 68 + ac + 4];
            uint32_t a3 = Ps[(ar + 8) * 68 + ac + 4];
#pragma unroll
            for (int j = 0; j < 8; j++) {
                const int br = kk * 8 + qt;
                const int bc = j * 8 + qg;
                uint32_t b0 = f2tf(Vs[br * 72 + bc]);
                uint32_t b1 = f2tf(Vs[(br + 4) * 72 + bc]);
                mma_tf32(oacc[j], a0, a1, a2, a3, b0, b1);
            }
        }
        __syncwarp();   // PV reads of Ps done before next tile's stores
    }

    // ---- epilogue ----
    const float inv0 = 1.f / lrow[0];
    const float inv1 = 1.f / lrow[1];
    float* oA = outp + (size_t)(b * T_ + ra) * E_ + h * D_;
    float* oB = outp + (size_t)(b * T_ + rb) * E_ + h * D_;
#pragma unroll
    for (int j = 0; j < 8; j++) {
        const int c = j * 8 + 2 * qt;
        float2 o0 = {oacc[j][0] * inv0, oacc[j][1] * inv0};
        float2 o1 = {oacc[j][2] * inv1, oacc[j][3] * inv1};
        *(float2*)(oA + c) = o0;
        *(float2*)(oB + c) = o1;
    }
}

// ---------------------------------------------------------------------------
extern "C" void kernel_launch(void* const* d_in, const int* in_sizes, int n_in,
                              void* d_out, int out_size)
{
    const float* query = (const float*)d_in[0];
    const float* key   = (const float*)d_in[1];
    const float* value = (const float*)d_in[2];
    const float* spatial = (const float*)d_in[3];
    const float* dirb    = (const float*)d_in[4];
    const unsigned char* pmask = (const unsigned char*)d_in[5];
    const float* amask = (const float*)d_in[6];
    const float* Wq = (const float*)d_in[7];
    const float* bq = (const float*)d_in[8];
    const float* Wk = (const float*)d_in[9];
    const float* bk = (const float*)d_in[10];
    const float* Wv = (const float*)d_in[11];
    const float* bv = (const float*)d_in[12];
    const float* Wo = (const float*)d_in[13];
    const float* bo = (const float*)d_in[14];
    float* out = (float*)d_out;

    float *qp, *kp, *vp, *ap;
    cudaGetSymbolAddress((void**)&qp, g_q);
    cudaGetSymbolAddress((void**)&kp, g_k);
    cudaGetSymbolAddress((void**)&vp, g_v);
    cudaGetSymbolAddress((void**)&ap, g_attn);

    cudaFuncSetAttribute(gemm_tc,
                         cudaFuncAttributeMaxDynamicSharedMemorySize,
                         GEMM_SMEM_BYTES);
    cudaFuncSetAttribute(attn_tc,
                         cudaFuncAttributeMaxDynamicSharedMemorySize,
                         ATTN_SMEM_BYTES);

    const dim3 gb(E_ / 64, M_ / 256);   // (16, 16)
    gemm_tc<<<gb, 256, GEMM_SMEM_BYTES>>>(query, Wq, bq, qp, 1);
    gemm_tc<<<gb, 256, GEMM_SMEM_BYTES>>>(key,   Wk, bk, kp, 1);
    gemm_tc<<<gb, 256, GEMM_SMEM_BYTES>>>(value, Wv, bv, vp, 1);

    attn_tc<<<dim3(T_ / 128, H_, B_), 256, ATTN_SMEM_BYTES>>>(
        spatial, dirb, amask, pmask, ap);

    gemm_tc<<<gb, 256, GEMM_SMEM_BYTES>>>(ap, Wo, bo, out, 0);
}